// round 1
// baseline (speedup 1.0000x reference)
#include <cuda_runtime.h>
#include <math.h>

#define FULL 0xffffffffu

// tn[b][n]: l2-normalized token projection, produced by token_kernel
__device__ float g_tn[32 * 128];

__device__ __forceinline__ float gelu_exact(float z) {
    return 0.5f * z * (1.0f + erff(z * 0.70710678118654752f));
}

// ---------------------------------------------------------------------------
// Kernel 1: token path.  tok = l2norm(gelu(LN1(token) @ w_tok + b_tok))
// Grid: 32 blocks (one per batch), 256 threads.
// ---------------------------------------------------------------------------
__global__ void token_kernel(const float* __restrict__ token,
                             const float* __restrict__ ln1_g,
                             const float* __restrict__ ln1_b,
                             const float* __restrict__ w_tok,
                             const float* __restrict__ b_tok)
{
    __shared__ float st[768];
    __shared__ float spart[256];
    __shared__ float sy[128];
    __shared__ float sred[8];
    __shared__ float sredq[8];

    const int b = blockIdx.x;
    const int tid = threadIdx.x;
    const int wid = tid >> 5, lane = tid & 31;
    const float* trow = token + b * 768;

    float s = 0.f, sq = 0.f;
    for (int i = tid; i < 768; i += 256) {
        float v = trow[i];
        st[i] = v;
        s += v; sq += v * v;
    }
    #pragma unroll
    for (int o = 16; o; o >>= 1) {
        s  += __shfl_down_sync(FULL, s,  o);
        sq += __shfl_down_sync(FULL, sq, o);
    }
    if (lane == 0) { sred[wid] = s; sredq[wid] = sq; }
    __syncthreads();
    if (tid == 0) {
        float ts = 0.f, tq = 0.f;
        #pragma unroll
        for (int i = 0; i < 8; i++) { ts += sred[i]; tq += sredq[i]; }
        sred[0] = ts; sredq[0] = tq;
    }
    __syncthreads();
    const float mean = sred[0] * (1.0f / 768.0f);
    const float var  = sredq[0] * (1.0f / 768.0f) - mean * mean;
    const float rstd = rsqrtf(var + 1e-6f);
    __syncthreads();   // all threads have read sred/sredq before st rewrite below

    for (int i = tid; i < 768; i += 256)
        st[i] = (st[i] - mean) * rstd * ln1_g[i] + ln1_b[i];
    __syncthreads();

    // GEMV: 256 threads = 128 outputs x 2 k-halves
    const int n = tid & 127, half = tid >> 7;
    const int k0 = half * 384;
    const float* wp = w_tok + n;
    float acc = 0.f;
    #pragma unroll 8
    for (int k = 0; k < 384; k++)
        acc += st[k0 + k] * wp[(size_t)(k0 + k) * 128];
    spart[tid] = acc;
    __syncthreads();

    if (tid < 128) {
        float z = spart[tid] + spart[tid + 128] + b_tok[tid];
        sy[tid] = gelu_exact(z);
    }
    __syncthreads();

    float q = 0.f;
    if (tid < 128) { float v = sy[tid]; q = v * v; }
    #pragma unroll
    for (int o = 16; o; o >>= 1) q += __shfl_down_sync(FULL, q, o);
    if (lane == 0) sred[wid] = q;
    __syncthreads();
    if (tid == 0) {
        float t = 0.f;
        #pragma unroll
        for (int i = 0; i < 8; i++) t += sred[i];
        sred[0] = t;
    }
    __syncthreads();
    if (tid < 128) {
        float nrm = sqrtf(sred[0]);
        g_tn[b * 128 + tid] = sy[tid] / fmaxf(nrm, 1e-12f);
    }
}

// ---------------------------------------------------------------------------
// Kernel 2: fused main path.
// Per block: 64 pixels of one batch.
//   Phase 1: row mean/var + LN2 into shared As
//   Phase 2: tiled GEMM As[64x192] @ w_x[192x128] (fp32 SIMT, 4x8 microtiles)
//   Epilogue: gelu, dot with tn, L2 norm -> attn -> sc = a*rsqrt(a^2 v + eps)
//   Phase 3: out = 0.5x + (x-m)*sc*g3 + b3
// ---------------------------------------------------------------------------
#define MT 64
#define KC 64
#define APAD 193
#define WPAD 132

__global__ void __launch_bounds__(256, 2) main_kernel(
    const float* __restrict__ x,
    const float* __restrict__ p,
    const float* __restrict__ alpha,
    const float* __restrict__ ln2_g, const float* __restrict__ ln2_b,
    const float* __restrict__ w_x,  const float* __restrict__ b_x,
    const float* __restrict__ ln3_g, const float* __restrict__ ln3_b,
    float* __restrict__ out)
{
    extern __shared__ float sm[];
    float* As    = sm;                      // [64][193]
    float* Ws    = As + MT * APAD;          // [64][132]
    float* smean = Ws + KC * WPAD;          // [64]
    float* svar  = smean + MT;              // [64]
    float* sdot  = svar + MT;               // [64]
    float* ssq   = sdot + MT;               // [64]
    float* sc    = ssq + MT;                // [64]
    float* stn   = sc + MT;                 // [128]
    float* sbx   = stn + 128;               // [128]
    float* sg2   = sbx + 128;               // [192]
    float* sb2   = sg2 + 192;               // [192]
    float* sg3   = sb2 + 192;               // [192]
    float* sb3   = sg3 + 192;               // [192]

    const int tid = threadIdx.x;
    const int bx = blockIdx.x;
    const int b = bx >> 6, tile = bx & 63;
    const size_t base = (size_t)(b * 4096 + tile * 64) * 192;
    const float* xb = x + base;
    float* ob = out + base;

    if (tid < 128) { stn[tid] = g_tn[b * 128 + tid]; sbx[tid] = b_x[tid]; }
    if (tid < 192) {
        sg2[tid] = ln2_g[tid]; sb2[tid] = ln2_b[tid];
        sg3[tid] = ln3_g[tid]; sb3[tid] = ln3_b[tid];
    }
    __syncthreads();

    // ---- Phase 1: per-row LN2 stats + normalized tile into As ----
    const int wid = tid >> 5, lane = tid & 31;
    #pragma unroll
    for (int rr = 0; rr < 8; rr++) {
        const int r = wid * 8 + rr;
        const float* xr = xb + r * 192;
        float v[6];
        float s = 0.f, sq = 0.f;
        #pragma unroll
        for (int j = 0; j < 6; j++) {
            v[j] = xr[j * 32 + lane];
            s += v[j]; sq += v[j] * v[j];
        }
        #pragma unroll
        for (int o = 16; o; o >>= 1) {
            s  += __shfl_down_sync(FULL, s,  o);
            sq += __shfl_down_sync(FULL, sq, o);
        }
        s  = __shfl_sync(FULL, s, 0);
        sq = __shfl_sync(FULL, sq, 0);
        const float mean = s * (1.0f / 192.0f);
        const float var  = sq * (1.0f / 192.0f) - mean * mean;
        const float rstd = rsqrtf(var + 1e-6f);
        if (lane == 0) { smean[r] = mean; svar[r] = var; }
        #pragma unroll
        for (int j = 0; j < 6; j++) {
            const int c = j * 32 + lane;
            As[r * APAD + c] = (v[j] - mean) * rstd * sg2[c] + sb2[c];
        }
    }
    __syncthreads();

    // ---- Phase 2: GEMM 64x128x192 ----
    const int tx = tid & 15, ty = tid >> 4;     // ty: 4-row group, tx: 8-col group
    float acc[4][8];
    #pragma unroll
    for (int i = 0; i < 4; i++)
        #pragma unroll
        for (int j = 0; j < 8; j++) acc[i][j] = 0.f;

    for (int kc = 0; kc < 192; kc += KC) {
        #pragma unroll 8
        for (int i = tid; i < KC * 128; i += 256)
            Ws[(i >> 7) * WPAD + (i & 127)] = w_x[(size_t)kc * 128 + i];
        __syncthreads();

        #pragma unroll 8
        for (int k = 0; k < KC; k++) {
            const float a0 = As[(ty * 4 + 0) * APAD + kc + k];
            const float a1 = As[(ty * 4 + 1) * APAD + kc + k];
            const float a2 = As[(ty * 4 + 2) * APAD + kc + k];
            const float a3 = As[(ty * 4 + 3) * APAD + kc + k];
            const float4 bv0 = *(const float4*)&Ws[k * WPAD + tx * 8];
            const float4 bv1 = *(const float4*)&Ws[k * WPAD + tx * 8 + 4];
            const float bb[8] = {bv0.x, bv0.y, bv0.z, bv0.w,
                                 bv1.x, bv1.y, bv1.z, bv1.w};
            #pragma unroll
            for (int j = 0; j < 8; j++) {
                acc[0][j] += a0 * bb[j];
                acc[1][j] += a1 * bb[j];
                acc[2][j] += a2 * bb[j];
                acc[3][j] += a3 * bb[j];
            }
        }
        __syncthreads();
    }

    // ---- Epilogue: gelu, dot with tn, sumsq -> attn scale ----
    float pd[4] = {0.f, 0.f, 0.f, 0.f};
    float pq[4] = {0.f, 0.f, 0.f, 0.f};
    #pragma unroll
    for (int i = 0; i < 4; i++) {
        #pragma unroll
        for (int j = 0; j < 8; j++) {
            const int n = tx * 8 + j;
            const float z = acc[i][j] + sbx[n];
            const float e = gelu_exact(z);
            pd[i] += e * stn[n];
            pq[i] += e * e;
        }
    }
    #pragma unroll
    for (int i = 0; i < 4; i++) {
        #pragma unroll
        for (int o = 8; o; o >>= 1) {
            pd[i] += __shfl_down_sync(FULL, pd[i], o, 16);
            pq[i] += __shfl_down_sync(FULL, pq[i], o, 16);
        }
    }
    if (tx == 0) {
        #pragma unroll
        for (int i = 0; i < 4; i++) {
            sdot[ty * 4 + i] = pd[i];
            ssq [ty * 4 + i] = pq[i];
        }
    }
    __syncthreads();

    if (tid < 64) {
        const float ps  = p[b] * expf(alpha[0]);
        const float nrm = sqrtf(ssq[tid]);
        const float a   = ps * sdot[tid] / fmaxf(nrm, 1e-12f);
        // LN3(a*x) = (x - m) * a * rsqrt(a^2 v + eps) * g3 + b3
        sc[tid] = a * rsqrtf(a * a * svar[tid] + 1e-6f);
    }
    __syncthreads();

    // ---- Phase 3: residual write ----
    for (int i = tid; i < MT * 192; i += 256) {
        const int r = i / 192;
        const int c = i - r * 192;
        const float xv = xb[i];            // L1-hot: same tile read in phase 1
        ob[i] = 0.5f * xv + (xv - smean[r]) * sc[r] * sg3[c] + sb3[c];
    }
}

// ---------------------------------------------------------------------------
extern "C" void kernel_launch(void* const* d_in, const int* in_sizes, int n_in,
                              void* d_out, int out_size)
{
    (void)in_sizes; (void)n_in; (void)out_size;
    const float* x     = (const float*)d_in[0];
    const float* token = (const float*)d_in[1];
    const float* p     = (const float*)d_in[2];
    const float* alpha = (const float*)d_in[3];
    const float* ln1_g = (const float*)d_in[4];
    const float* ln1_b = (const float*)d_in[5];
    const float* w_tok = (const float*)d_in[6];
    const float* b_tok = (const float*)d_in[7];
    const float* ln2_g = (const float*)d_in[8];
    const float* ln2_b = (const float*)d_in[9];
    const float* w_x   = (const float*)d_in[10];
    const float* b_x   = (const float*)d_in[11];
    const float* ln3_g = (const float*)d_in[12];
    const float* ln3_b = (const float*)d_in[13];
    float* out = (float*)d_out;

    token_kernel<<<32, 256>>>(token, ln1_g, ln1_b, w_tok, b_tok);

    const size_t smem = (MT * APAD + KC * WPAD + 5 * MT + 2 * 128 + 4 * 192) * sizeof(float);
    cudaFuncSetAttribute(main_kernel, cudaFuncAttributeMaxDynamicSharedMemorySize, (int)smem);
    main_kernel<<<2048, 256, smem>>>(x, p, alpha, ln2_g, ln2_b, w_x, b_x,
                                     ln3_g, ln3_b, out);
}

// round 2
// speedup vs baseline: 2.1644x; 2.1644x over previous
#include <cuda_runtime.h>
#include <math.h>
#include <stdint.h>

#define FULL 0xffffffffu

// tn[b][n]: l2-normalized token projection, produced by token_kernel
__device__ float g_tn[32 * 128];

__device__ __forceinline__ float gelu_exact(float z) {
    return 0.5f * z * (1.0f + erff(z * 0.70710678118654752f));
}

__device__ __forceinline__ uint32_t f2tf32(float f) {
    uint32_t u;
    asm("cvt.rna.tf32.f32 %0, %1;" : "=r"(u) : "f"(f));
    return u;
}

__device__ __forceinline__ void mma_tf32(float* c,
                                         uint32_t a0, uint32_t a1, uint32_t a2, uint32_t a3,
                                         uint32_t b0, uint32_t b1) {
    asm volatile(
        "mma.sync.aligned.m16n8k8.row.col.f32.tf32.tf32.f32 "
        "{%0,%1,%2,%3}, {%4,%5,%6,%7}, {%8,%9}, {%0,%1,%2,%3};\n"
        : "+f"(c[0]), "+f"(c[1]), "+f"(c[2]), "+f"(c[3])
        : "r"(a0), "r"(a1), "r"(a2), "r"(a3), "r"(b0), "r"(b1));
}

// ---------------------------------------------------------------------------
// Kernel 1: token path.  tok = l2norm(gelu(LN1(token) @ w_tok + b_tok))
// ---------------------------------------------------------------------------
__global__ void token_kernel(const float* __restrict__ token,
                             const float* __restrict__ ln1_g,
                             const float* __restrict__ ln1_b,
                             const float* __restrict__ w_tok,
                             const float* __restrict__ b_tok)
{
    __shared__ float st[768];
    __shared__ float spart[256];
    __shared__ float sy[128];
    __shared__ float sred[8];
    __shared__ float sredq[8];

    const int b = blockIdx.x;
    const int tid = threadIdx.x;
    const int wid = tid >> 5, lane = tid & 31;
    const float* trow = token + b * 768;

    float s = 0.f, sq = 0.f;
    for (int i = tid; i < 768; i += 256) {
        float v = trow[i];
        st[i] = v;
        s += v; sq += v * v;
    }
    #pragma unroll
    for (int o = 16; o; o >>= 1) {
        s  += __shfl_down_sync(FULL, s,  o);
        sq += __shfl_down_sync(FULL, sq, o);
    }
    if (lane == 0) { sred[wid] = s; sredq[wid] = sq; }
    __syncthreads();
    if (tid == 0) {
        float ts = 0.f, tq = 0.f;
        #pragma unroll
        for (int i = 0; i < 8; i++) { ts += sred[i]; tq += sredq[i]; }
        sred[0] = ts; sredq[0] = tq;
    }
    __syncthreads();
    const float mean = sred[0] * (1.0f / 768.0f);
    const float var  = sredq[0] * (1.0f / 768.0f) - mean * mean;
    const float rstd = rsqrtf(var + 1e-6f);
    __syncthreads();

    for (int i = tid; i < 768; i += 256)
        st[i] = (st[i] - mean) * rstd * ln1_g[i] + ln1_b[i];
    __syncthreads();

    const int n = tid & 127, half = tid >> 7;
    const int k0 = half * 384;
    const float* wp = w_tok + n;
    float acc = 0.f;
    #pragma unroll 8
    for (int k = 0; k < 384; k++)
        acc += st[k0 + k] * wp[(size_t)(k0 + k) * 128];
    spart[tid] = acc;
    __syncthreads();

    if (tid < 128) {
        float z = spart[tid] + spart[tid + 128] + b_tok[tid];
        sy[tid] = gelu_exact(z);
    }
    __syncthreads();

    float q = 0.f;
    if (tid < 128) { float v = sy[tid]; q = v * v; }
    #pragma unroll
    for (int o = 16; o; o >>= 1) q += __shfl_down_sync(FULL, q, o);
    if (lane == 0) sred[wid] = q;
    __syncthreads();
    if (tid == 0) {
        float t = 0.f;
        #pragma unroll
        for (int i = 0; i < 8; i++) t += sred[i];
        sred[0] = t;
    }
    __syncthreads();
    if (tid < 128) {
        float nrm = sqrtf(sred[0]);
        g_tn[b * 128 + tid] = sy[tid] / fmaxf(nrm, 1e-12f);
    }
}

// ---------------------------------------------------------------------------
// Kernel 2: fused main path with tf32 tensor-core GEMM.
// Per block: 64 pixels.  8 warps = 4 rowgroups(16) x 2 colgroups(64).
// ---------------------------------------------------------------------------
#define MT 64
#define KC 64
#define APAD 196
#define WPAD 136

__global__ void __launch_bounds__(256, 2) main_kernel(
    const float* __restrict__ x,
    const float* __restrict__ p,
    const float* __restrict__ alpha,
    const float* __restrict__ ln2_g, const float* __restrict__ ln2_b,
    const float* __restrict__ w_x,  const float* __restrict__ b_x,
    const float* __restrict__ ln3_g, const float* __restrict__ ln3_b,
    float* __restrict__ out)
{
    extern __shared__ float sm[];
    float* As    = sm;                      // [64][196]  (tf32 bit patterns)
    float* Ws    = As + MT * APAD;          // [64][136]  (tf32 bit patterns)
    float* smean = Ws + KC * WPAD;          // [64]
    float* svar  = smean + MT;              // [64]
    float* sdotp = svar + MT;               // [2][64]
    float* ssqp  = sdotp + 128;             // [2][64]
    float* sc    = ssqp + 128;              // [64]
    float* stn   = sc + MT;                 // [128]
    float* sbx   = stn + 128;               // [128]
    float* sg2   = sbx + 128;               // [192]
    float* sb2   = sg2 + 192;               // [192]
    float* sg3   = sb2 + 192;               // [192]
    float* sb3   = sg3 + 192;               // [192]

    const int tid = threadIdx.x;
    const int bx = blockIdx.x;
    const int b = bx >> 6, tile = bx & 63;
    const size_t base = (size_t)(b * 4096 + tile * 64) * 192;
    const float* xb = x + base;
    float* ob = out + base;

    if (tid < 128) { stn[tid] = g_tn[b * 128 + tid]; sbx[tid] = b_x[tid]; }
    if (tid < 192) {
        sg2[tid] = ln2_g[tid]; sb2[tid] = ln2_b[tid];
        sg3[tid] = ln3_g[tid]; sb3[tid] = ln3_b[tid];
    }
    __syncthreads();

    // ---- Phase 1: per-row LN2 stats + normalized tile into As (tf32) ----
    const int wid = tid >> 5, lane = tid & 31;
    uint32_t* Asu = (uint32_t*)As;
    uint32_t* Wsu = (uint32_t*)Ws;
    #pragma unroll
    for (int rr = 0; rr < 8; rr++) {
        const int r = wid * 8 + rr;
        const float* xr = xb + r * 192;
        float v[6];
        float s = 0.f, sq = 0.f;
        #pragma unroll
        for (int j = 0; j < 6; j++) {
            v[j] = xr[j * 32 + lane];
            s += v[j]; sq += v[j] * v[j];
        }
        #pragma unroll
        for (int o = 16; o; o >>= 1) {
            s  += __shfl_down_sync(FULL, s,  o);
            sq += __shfl_down_sync(FULL, sq, o);
        }
        s  = __shfl_sync(FULL, s, 0);
        sq = __shfl_sync(FULL, sq, 0);
        const float mean = s * (1.0f / 192.0f);
        const float var  = sq * (1.0f / 192.0f) - mean * mean;
        const float rstd = rsqrtf(var + 1e-6f);
        if (lane == 0) { smean[r] = mean; svar[r] = var; }
        #pragma unroll
        for (int j = 0; j < 6; j++) {
            const int c = j * 32 + lane;
            Asu[r * APAD + c] = f2tf32((v[j] - mean) * rstd * sg2[c] + sb2[c]);
        }
    }
    __syncthreads();

    // ---- Phase 2: tf32 tensor GEMM 64x128x192 ----
    const int rowg = wid >> 1, colg = wid & 1;
    const int qrow = lane >> 2, kq = lane & 3;

    float acc[8][4];
    #pragma unroll
    for (int t = 0; t < 8; t++)
        #pragma unroll
        for (int i = 0; i < 4; i++) acc[t][i] = 0.f;

    for (int kc = 0; kc < 192; kc += KC) {
        // stage w_x chunk [KC x 128] into Ws (tf32)
        const float4* wg = (const float4*)(w_x + (size_t)kc * 128);
        #pragma unroll
        for (int i = tid; i < KC * 32; i += 256) {
            const int row = i >> 5, c4 = i & 31;
            float4 v = wg[row * 32 + c4];
            uint4 u;
            u.x = f2tf32(v.x); u.y = f2tf32(v.y);
            u.z = f2tf32(v.z); u.w = f2tf32(v.w);
            *(uint4*)&Wsu[row * WPAD + c4 * 4] = u;
        }
        __syncthreads();

        #pragma unroll
        for (int ks = 0; ks < 8; ks++) {
            const int k0 = kc + ks * 8;
            const uint32_t a0 = Asu[(rowg * 16 + qrow)     * APAD + k0 + kq];
            const uint32_t a1 = Asu[(rowg * 16 + qrow + 8) * APAD + k0 + kq];
            const uint32_t a2 = Asu[(rowg * 16 + qrow)     * APAD + k0 + kq + 4];
            const uint32_t a3 = Asu[(rowg * 16 + qrow + 8) * APAD + k0 + kq + 4];
            #pragma unroll
            for (int t = 0; t < 8; t++) {
                const int col = colg * 64 + t * 8 + qrow;
                const uint32_t b0 = Wsu[(ks * 8 + kq)     * WPAD + col];
                const uint32_t b1 = Wsu[(ks * 8 + kq + 4) * WPAD + col];
                mma_tf32(acc[t], a0, a1, a2, a3, b0, b1);
            }
        }
        __syncthreads();
    }

    // ---- Epilogue: gelu, dot with tn, sumsq ----
    {
        float dlo = 0.f, qlo = 0.f, dhi = 0.f, qhi = 0.f;
        #pragma unroll
        for (int t = 0; t < 8; t++) {
            #pragma unroll
            for (int c = 0; c < 2; c++) {
                const int col = colg * 64 + t * 8 + kq * 2 + c;
                const float tnv = stn[col], bxv = sbx[col];
                const float elo = gelu_exact(acc[t][c] + bxv);
                const float ehi = gelu_exact(acc[t][2 + c] + bxv);
                dlo += elo * tnv; qlo += elo * elo;
                dhi += ehi * tnv; qhi += ehi * ehi;
            }
        }
        #pragma unroll
        for (int o = 1; o < 4; o <<= 1) {
            dlo += __shfl_xor_sync(FULL, dlo, o);
            qlo += __shfl_xor_sync(FULL, qlo, o);
            dhi += __shfl_xor_sync(FULL, dhi, o);
            qhi += __shfl_xor_sync(FULL, qhi, o);
        }
        if (kq == 0) {
            const int rlo = rowg * 16 + qrow, rhi = rlo + 8;
            sdotp[colg * 64 + rlo] = dlo; ssqp[colg * 64 + rlo] = qlo;
            sdotp[colg * 64 + rhi] = dhi; ssqp[colg * 64 + rhi] = qhi;
        }
    }
    __syncthreads();

    if (tid < 64) {
        const float dot = sdotp[tid] + sdotp[64 + tid];
        const float ssq = ssqp[tid]  + ssqp[64 + tid];
        const float ps  = p[b] * expf(alpha[0]);
        const float a   = ps * dot / fmaxf(sqrtf(ssq), 1e-12f);
        // LN3(a*x) = (x - m) * a * rsqrt(a^2 v + eps) * g3 + b3
        sc[tid] = a * rsqrtf(a * a * svar[tid] + 1e-6f);
    }
    __syncthreads();

    // ---- Phase 3: residual write (float4) ----
    const float4* xb4 = (const float4*)xb;
    float4* ob4 = (float4*)ob;
    #pragma unroll
    for (int i = tid; i < MT * 48; i += 256) {
        const int r = i / 48;
        const int c = (i - r * 48) * 4;
        const float4 xv = xb4[i];
        const float m = smean[r], scv = sc[r];
        float4 o;
        o.x = 0.5f * xv.x + (xv.x - m) * scv * sg3[c]     + sb3[c];
        o.y = 0.5f * xv.y + (xv.y - m) * scv * sg3[c + 1] + sb3[c + 1];
        o.z = 0.5f * xv.z + (xv.z - m) * scv * sg3[c + 2] + sb3[c + 2];
        o.w = 0.5f * xv.w + (xv.w - m) * scv * sg3[c + 3] + sb3[c + 3];
        ob4[i] = o;
    }
}

// ---------------------------------------------------------------------------
extern "C" void kernel_launch(void* const* d_in, const int* in_sizes, int n_in,
                              void* d_out, int out_size)
{
    (void)in_sizes; (void)n_in; (void)out_size;
    const float* x     = (const float*)d_in[0];
    const float* token = (const float*)d_in[1];
    const float* p     = (const float*)d_in[2];
    const float* alpha = (const float*)d_in[3];
    const float* ln1_g = (const float*)d_in[4];
    const float* ln1_b = (const float*)d_in[5];
    const float* w_tok = (const float*)d_in[6];
    const float* b_tok = (const float*)d_in[7];
    const float* ln2_g = (const float*)d_in[8];
    const float* ln2_b = (const float*)d_in[9];
    const float* w_x   = (const float*)d_in[10];
    const float* b_x   = (const float*)d_in[11];
    const float* ln3_g = (const float*)d_in[12];
    const float* ln3_b = (const float*)d_in[13];
    float* out = (float*)d_out;

    token_kernel<<<32, 256>>>(token, ln1_g, ln1_b, w_tok, b_tok);

    const size_t smem = (MT * APAD + KC * WPAD + 2 * MT + 2 * 128 + MT + MT
                         + 2 * 128 + 4 * 192) * sizeof(float);
    cudaFuncSetAttribute(main_kernel, cudaFuncAttributeMaxDynamicSharedMemorySize, (int)smem);
    main_kernel<<<2048, 256, smem>>>(x, p, alpha, ln2_g, ln2_b, w_x, b_x,
                                     ln3_g, ln3_b, out);
}